// round 9
// baseline (speedup 1.0000x reference)
#include <cuda_runtime.h>
#include <stdint.h>

// Batched upper-triangular scatter:
//   out[b, r, c] = in[b, r*M - r*(r-1)/2 + (c-r)]  if c >= r, else 0
// M = 1024, TRIU = 524800, B = 128.
//
// Pure bandwidth kernel: 256 MiB read + 512 MiB write (both mandatory).
// R8: 256-bit stores (st.global.cs.v8.f32, STG.256 on sm_103a) on the
// 32B-aligned output; loads stay scalar __ldcs (input is only 4B-aligned).
// ROWS=2 per 128-thr block keeps regs ~28 -> full occupancy possible.

#define MAT_M 1024
#define TRIU_LEN 524800
#define ROWS_PER_BLK 2

__device__ __forceinline__ void stcs_v8(float* p, const float* v) {
    asm volatile(
        "st.global.cs.v8.f32 [%0], {%1, %2, %3, %4, %5, %6, %7, %8};"
        :: "l"(p),
           "f"(v[0]), "f"(v[1]), "f"(v[2]), "f"(v[3]),
           "f"(v[4]), "f"(v[5]), "f"(v[6]), "f"(v[7])
        : "memory");
}

__global__ void __launch_bounds__(128, 16)
triu_scatter_kernel(const float* __restrict__ in, float* __restrict__ out)
{
    const int r0 = blockIdx.x * ROWS_PER_BLK;   // 0,2,...,1022
    const int b  = blockIdx.y;                  // 0..B-1
    const int c0 = threadIdx.x << 3;            // 0,8,...,1016

    const float* __restrict__ inb = in + (size_t)b * TRIU_LEN;

    float v[ROWS_PER_BLK][8];

    // ---- Phase 1: front-batched scalar loads (independent -> deep MLP) ----
    #pragma unroll
    for (int j = 0; j < ROWS_PER_BLK; ++j) {
        const int r = r0 + j;
        // rowstart = r*M - r*(r-1)/2, max 524799 (fits int)
        const int rowstart = r * MAT_M - ((r * (r - 1)) >> 1);

        if (c0 >= r) {
            // Fully inside upper triangle: contiguous packed loads.
            const float* p = inb + rowstart + (c0 - r);
            #pragma unroll
            for (int k = 0; k < 8; ++k) v[j][k] = __ldcs(p + k);
        } else if (c0 + 7 < r) {
            // Fully below diagonal: pure zero store, no read.
            #pragma unroll
            for (int k = 0; k < 8; ++k) v[j][k] = 0.f;
        } else {
            // Straddles the diagonal (<=1 thread per row).
            #pragma unroll
            for (int k = 0; k < 8; ++k) {
                const int c = c0 + k;
                v[j][k] = (c >= r) ? __ldcs(inb + rowstart + (c - r)) : 0.f;
            }
        }
    }

    // ---- Phase 2: 32B-aligned 256-bit streaming stores ----
    const size_t base = (((size_t)b * MAT_M + (size_t)r0) * MAT_M) + (size_t)c0;
    #pragma unroll
    for (int j = 0; j < ROWS_PER_BLK; ++j) {
        stcs_v8(out + base + (size_t)j * MAT_M, v[j]);
    }
}

extern "C" void kernel_launch(void* const* d_in, const int* in_sizes, int n_in,
                              void* d_out, int out_size)
{
    const float* in = (const float*)d_in[0];
    float* out = (float*)d_out;

    const int B = in_sizes[0] / TRIU_LEN;   // 128 for the bench shape

    dim3 grid(MAT_M / ROWS_PER_BLK, B);
    dim3 block(128);
    triu_scatter_kernel<<<grid, block>>>(in, out);
}

// round 10
// speedup vs baseline: 1.0175x; 1.0175x over previous
#include <cuda_runtime.h>
#include <stdint.h>

// Batched upper-triangular scatter:
//   out[b, r, c] = in[b, r*M - r*(r-1)/2 + (c-r)]  if c >= r, else 0
// M = 1024, TRIU = 524800, B = 128.
//
// Pure bandwidth kernel at the traffic floor: 256 MiB read (input read
// exactly once, contiguously — packed rows abut) + 512 MiB write (every
// output byte mandatory; harness poisons d_out). Converged champion config:
// 4 rows per block, 256 threads, front-batched MLP=4 float4 loads,
// streaming (.cs) loads+stores. Measured 82% of DRAM peak (6.5 TB/s) —
// the mixed 1:2 R:W HBM turnaround ceiling; occupancy/width/policy
// variants all land at or below this.

#define MAT_M 1024
#define TRIU_LEN 524800
#define ROWS_PER_BLK 4

__device__ __forceinline__ float4 ldcs4(const float* p) {
    float4 v;
    v.x = __ldcs(p + 0);
    v.y = __ldcs(p + 1);
    v.z = __ldcs(p + 2);
    v.w = __ldcs(p + 3);
    return v;
}

__global__ void __launch_bounds__(256, 8)
triu_scatter_kernel(const float* __restrict__ in, float* __restrict__ out)
{
    const int r0 = blockIdx.x * ROWS_PER_BLK;   // 0,4,...,1020
    const int b  = blockIdx.y;                  // 0..B-1
    const int c0 = threadIdx.x << 2;            // 0,4,...,1020

    const float* __restrict__ inb = in + (size_t)b * TRIU_LEN;

    float4 v[ROWS_PER_BLK];

    // ---- Phase 1: batch all loads (independent -> MLP=4) ----
    #pragma unroll
    for (int j = 0; j < ROWS_PER_BLK; ++j) {
        const int r = r0 + j;
        // rowstart = r*M - r*(r-1)/2, max 524799 (fits int)
        const int rowstart = r * MAT_M - ((r * (r - 1)) >> 1);

        if (c0 >= r) {
            // Fully inside upper triangle: contiguous packed load.
            v[j] = ldcs4(inb + rowstart + (c0 - r));
        } else if (c0 + 3 < r) {
            // Fully below diagonal: pure zero store, no read.
            v[j] = make_float4(0.f, 0.f, 0.f, 0.f);
        } else {
            // Straddles the diagonal (<=1 thread per row).
            float t[4];
            #pragma unroll
            for (int k = 0; k < 4; ++k) {
                const int c = c0 + k;
                t[k] = (c >= r) ? __ldcs(inb + rowstart + (c - r)) : 0.f;
            }
            v[j] = make_float4(t[0], t[1], t[2], t[3]);
        }
    }

    // ---- Phase 2: aligned streaming float4 stores ----
    const size_t base = (((size_t)b * MAT_M + (size_t)r0) * MAT_M) + (size_t)c0;
    #pragma unroll
    for (int j = 0; j < ROWS_PER_BLK; ++j) {
        __stcs(reinterpret_cast<float4*>(out + base + (size_t)j * MAT_M), v[j]);
    }
}

extern "C" void kernel_launch(void* const* d_in, const int* in_sizes, int n_in,
                              void* d_out, int out_size)
{
    const float* in = (const float*)d_in[0];
    float* out = (float*)d_out;

    const int B = in_sizes[0] / TRIU_LEN;   // 128 for the bench shape

    dim3 grid(MAT_M / ROWS_PER_BLK, B);
    dim3 block(256);
    triu_scatter_kernel<<<grid, block>>>(in, out);
}